// round 2
// baseline (speedup 1.0000x reference)
#include <cuda_runtime.h>
#include <math.h>
#include <stdint.h>

#define T_STEPS 2048
#define BATCH   64
#define IN_DIM  64
#define HID     512
#define O_DIM   32
#define OC_DIM  8

// Scratch: pre[t,b,h] = x@WiT + bi + bh + nscale*noise  (256 MB, static device array)
__device__ float g_pre[(size_t)T_STEPS * BATCH * HID];

// ---------------------------------------------------------------------------
// Kernel A: pre-projection GEMM  [TB=131072, 64] x WiT[64, 512] + biases + noise
// grid (2048, 8): x = 64-row m-tile, y = 64-col h-tile. 256 threads.
// SMEM: xs 16KB + wT 17KB = 33.4KB static (under 48KB limit).
// ---------------------------------------------------------------------------
__global__ void pre_kernel(const float* __restrict__ x,
                           const float* __restrict__ Wi,
                           const float* __restrict__ bi,
                           const float* __restrict__ bh,
                           const float* __restrict__ noise) {
    __shared__ float xs[64][64];
    __shared__ float wT[64][68];   // [k][h_local], row pad 68 floats

    const float NSCALE = sqrtf(45.0f / 512.0f);   // sqrt(2*sigma^2/alpha), exact
    const int m0  = blockIdx.x * 64;
    const int h0  = blockIdx.y * 64;
    const int tid = threadIdx.x;

    // load x tile (coalesced float4): 64*64 floats = 1024 float4
    const float4* x4 = (const float4*)(x + (size_t)m0 * IN_DIM);
    float4* xs4 = (float4*)xs;
#pragma unroll
    for (int i = 0; i < 4; i++) xs4[tid + 256 * i] = x4[tid + 256 * i];

    // load Wi rows [h0, h0+64) transposed into wT[k][h]
    for (int i = tid; i < 4096; i += 256) {
        int h = i >> 6, k = i & 63;
        wT[k][h] = Wi[(size_t)(h0 + h) * IN_DIM + k];
    }
    __syncthreads();

    const int hq = tid & 15;   // 4 h per thread
    const int ms = tid >> 4;   // 4 m per thread

    float acc[4][4];
#pragma unroll
    for (int j = 0; j < 4; j++) { acc[j][0] = acc[j][1] = acc[j][2] = acc[j][3] = 0.f; }

#pragma unroll 8
    for (int k = 0; k < 64; k++) {
        float4 w = *(const float4*)&wT[k][hq * 4];
#pragma unroll
        for (int j = 0; j < 4; j++) {
            float xv = xs[ms * 4 + j][k];
            acc[j][0] = fmaf(w.x, xv, acc[j][0]);
            acc[j][1] = fmaf(w.y, xv, acc[j][1]);
            acc[j][2] = fmaf(w.z, xv, acc[j][2]);
            acc[j][3] = fmaf(w.w, xv, acc[j][3]);
        }
    }

    float4 biv = *(const float4*)&bi[h0 + hq * 4];
    float4 bhv = *(const float4*)&bh[h0 + hq * 4];
    float bx = biv.x + bhv.x, by = biv.y + bhv.y, bz = biv.z + bhv.z, bw = biv.w + bhv.w;

#pragma unroll
    for (int j = 0; j < 4; j++) {
        int m = m0 + ms * 4 + j;
        size_t off = (size_t)m * HID + h0 + hq * 4;
        float4 nv = *(const float4*)&noise[off];
        float4 r;
        r.x = acc[j][0] + bx + NSCALE * nv.x;
        r.y = acc[j][1] + by + NSCALE * nv.y;
        r.z = acc[j][2] + bz + NSCALE * nv.z;
        r.w = acc[j][3] + bw + NSCALE * nv.w;
        *(float4*)&g_pre[off] = r;
    }
}

// ---------------------------------------------------------------------------
// Kernel B: sequential recurrence. 16 clusters x 8 CTAs, 256 threads/CTA.
// Cluster c handles batches 4c..4c+3; CTA rank r holds Wh rows [64r, 64r+64)
// SMEM-resident (k-quad-major). Per step: k-split GEMM, reduce, tanh-update,
// DSMEM broadcast of rate slice, cluster barrier. Double-buffered rate.
// ---------------------------------------------------------------------------
#define SMEM_WHS   (HID * 64)          // 32768 floats
#define SMEM_RATE  (2 * 4 * HID)       // 4096 floats (double buffer)
#define SMEM_PART  (16 * 64)           // 1024 floats
#define SMEM_B_FLOATS (SMEM_WHS + SMEM_RATE + SMEM_PART)
#define SMEM_B_BYTES  (SMEM_B_FLOATS * 4)

__device__ __forceinline__ void st_cluster_f32(uint32_t laddr, uint32_t rank, float v) {
    uint32_t ra;
    asm volatile("mapa.shared::cluster.u32 %0, %1, %2;" : "=r"(ra) : "r"(laddr), "r"(rank));
    asm volatile("st.shared::cluster.f32 [%0], %1;" :: "r"(ra), "f"(v) : "memory");
}

__device__ __forceinline__ void cluster_sync_() {
    asm volatile("barrier.cluster.arrive.aligned;" ::: "memory");
    asm volatile("barrier.cluster.wait.aligned;" ::: "memory");
}

__global__ void __launch_bounds__(256, 1) __cluster_dims__(8, 1, 1)
rnn_kernel(const float* __restrict__ rate0,
           const float* __restrict__ Wh,
           float* __restrict__ rate_all) {
    extern __shared__ float smem[];
    float* Whs    = smem;                       // k-quad-major: [(k>>2)][hl][k&3]
    float* rate_s = smem + SMEM_WHS;            // [buf][b][k]
    float* part   = rate_s + SMEM_RATE;         // [ks*4+b][hl]

    const int tid    = threadIdx.x;
    const int rank   = blockIdx.x & 7;
    const int cid    = blockIdx.x >> 3;
    const int b0     = cid * 4;
    const int h_base = rank * 64;

    // Load Wh slice (rows h_base..h_base+63) into quad-major SMEM layout.
    for (int i = tid; i < 64 * HID; i += 256) {
        int hl = i & 63, k = i >> 6;
        float v = Wh[(size_t)(h_base + hl) * HID + k];
        Whs[(k >> 2) * 256 + hl * 4 + (k & 3)] = v;
    }
    // Load initial rate (full 512-wide, 4 batches) into buffer 0.
    for (int i = tid; i < 4 * HID; i += 256) {
        rate_s[i] = rate0[(size_t)(b0 + (i >> 9)) * HID + (i & 511)];
    }
    __syncthreads();
    cluster_sync_();

    const int ks = tid >> 6;       // k-chunk 0..3 (128 k each)
    const int hl = tid & 63;       // h within slice
    const int ub = ks;             // update phase: batch 0..3
    const int uh = hl;             // update phase: h within slice
    const int hg = h_base + uh;    // global h

    const uint32_t rs_u32 = (uint32_t)__cvta_generic_to_shared(rate_s);
    const float4* wbase = (const float4*)Whs + (size_t)ks * 32 * 64 + hl;

    const float OMA   = 1.0f - 0.1f;
    const float ALPHA = 0.1f;

    float pre_next = g_pre[(size_t)(b0 + ub) * HID + hg];   // t = 0

    for (int t = 0; t < T_STEPS; t++) {
        const int cur = t & 1, nxt = cur ^ 1;
        const float pre_cur = pre_next;
        if (t < T_STEPS - 1)
            pre_next = g_pre[((size_t)(t + 1) * BATCH + b0 + ub) * HID + hg];

        const float* rb  = rate_s + cur * 2048;
        const float4* r0 = (const float4*)(rb + 0 * HID + ks * 128);
        const float4* r1 = (const float4*)(rb + 1 * HID + ks * 128);
        const float4* r2 = (const float4*)(rb + 2 * HID + ks * 128);
        const float4* r3 = (const float4*)(rb + 3 * HID + ks * 128);

        float a0 = 0.f, a1 = 0.f, a2 = 0.f, a3 = 0.f;
#pragma unroll 8
        for (int q = 0; q < 32; q++) {
            float4 w  = wbase[q * 64];
            float4 v0 = r0[q], v1 = r1[q], v2 = r2[q], v3 = r3[q];
            a0 = fmaf(w.x, v0.x, a0); a0 = fmaf(w.y, v0.y, a0);
            a0 = fmaf(w.z, v0.z, a0); a0 = fmaf(w.w, v0.w, a0);
            a1 = fmaf(w.x, v1.x, a1); a1 = fmaf(w.y, v1.y, a1);
            a1 = fmaf(w.z, v1.z, a1); a1 = fmaf(w.w, v1.w, a1);
            a2 = fmaf(w.x, v2.x, a2); a2 = fmaf(w.y, v2.y, a2);
            a2 = fmaf(w.z, v2.z, a2); a2 = fmaf(w.w, v2.w, a2);
            a3 = fmaf(w.x, v3.x, a3); a3 = fmaf(w.y, v3.y, a3);
            a3 = fmaf(w.z, v3.z, a3); a3 = fmaf(w.w, v3.w, a3);
        }
        part[(ks * 4 + 0) * 64 + hl] = a0;
        part[(ks * 4 + 1) * 64 + hl] = a1;
        part[(ks * 4 + 2) * 64 + hl] = a2;
        part[(ks * 4 + 3) * 64 + hl] = a3;
        __syncthreads();

        float s = part[(0 * 4 + ub) * 64 + uh]
                + part[(1 * 4 + ub) * 64 + uh]
                + part[(2 * 4 + ub) * 64 + uh]
                + part[(3 * 4 + ub) * 64 + uh]
                + pre_cur;
        float prev = rb[ub * HID + hg];
        float rnew = fmaf(OMA, prev, ALPHA * tanhf(s));

        rate_all[((size_t)t * BATCH + b0 + ub) * HID + hg] = rnew;

        uint32_t laddr = rs_u32 + (uint32_t)(nxt * 2048 + ub * HID + hg) * 4u;
#pragma unroll
        for (int p = 0; p < 8; p++) st_cluster_f32(laddr, (uint32_t)p, rnew);

        cluster_sync_();
    }
}

// ---------------------------------------------------------------------------
// Kernel C: readouts. One block per 4 (t,b) rows; 64 threads (32 for Wo, 8 for Woc).
// ---------------------------------------------------------------------------
__global__ void readout_kernel(const float* __restrict__ rate_all,
                               const float* __restrict__ Wo,
                               const float* __restrict__ bo,
                               const float* __restrict__ Woc,
                               const float* __restrict__ boc,
                               float* __restrict__ out,
                               float* __restrict__ outc) {
    __shared__ float4 rs[4][128];
    const int row0 = blockIdx.x * 4;
    const int tid  = threadIdx.x;   // 64

    const float4* r4 = (const float4*)(rate_all + (size_t)row0 * HID);
#pragma unroll
    for (int i = 0; i < 8; i++) {
        int idx = tid + 64 * i;
        rs[idx >> 7][idx & 127] = r4[idx];
    }
    __syncthreads();

    if (tid < O_DIM) {
        const float4* w4 = (const float4*)(Wo + (size_t)tid * HID);
        float b = bo[tid];
        float a[4] = {b, b, b, b};
#pragma unroll 4
        for (int k = 0; k < 128; k++) {
            float4 w = w4[k];
#pragma unroll
            for (int r = 0; r < 4; r++) {
                float4 v = rs[r][k];
                a[r] = fmaf(w.x, v.x, a[r]);
                a[r] = fmaf(w.y, v.y, a[r]);
                a[r] = fmaf(w.z, v.z, a[r]);
                a[r] = fmaf(w.w, v.w, a[r]);
            }
        }
#pragma unroll
        for (int r = 0; r < 4; r++)
            out[(size_t)(row0 + r) * O_DIM + tid] = a[r];
    } else if (tid < O_DIM + OC_DIM) {
        const int oc = tid - O_DIM;
        const float4* w4 = (const float4*)(Woc + (size_t)oc * HID);
        float b = boc[oc];
        float a[4] = {b, b, b, b};
#pragma unroll 4
        for (int k = 0; k < 128; k++) {
            float4 w = w4[k];
#pragma unroll
            for (int r = 0; r < 4; r++) {
                float4 v = rs[r][k];
                a[r] = fmaf(w.x, v.x, a[r]);
                a[r] = fmaf(w.y, v.y, a[r]);
                a[r] = fmaf(w.z, v.z, a[r]);
                a[r] = fmaf(w.w, v.w, a[r]);
            }
        }
#pragma unroll
        for (int r = 0; r < 4; r++)
            outc[(size_t)(row0 + r) * OC_DIM + oc] = a[r];
    }
}

// ---------------------------------------------------------------------------
extern "C" void kernel_launch(void* const* d_in, const int* in_sizes, int n_in,
                              void* d_out, int out_size) {
    const float* x     = (const float*)d_in[0];
    const float* rate0 = (const float*)d_in[1];
    const float* noise = (const float*)d_in[2];
    const float* Wi    = (const float*)d_in[3];
    const float* bi    = (const float*)d_in[4];
    const float* Wh    = (const float*)d_in[5];
    const float* bh    = (const float*)d_in[6];
    const float* Wo    = (const float*)d_in[7];
    const float* bo    = (const float*)d_in[8];
    const float* Woc   = (const float*)d_in[9];
    const float* boc   = (const float*)d_in[10];

    float* out      = (float*)d_out;
    float* outc     = out  + (size_t)T_STEPS * BATCH * O_DIM;
    float* rate_all = outc + (size_t)T_STEPS * BATCH * OC_DIM;

    // Phase 1: parallel pre-projection
    pre_kernel<<<dim3(2048, 8), 256>>>(x, Wi, bi, bh, noise);

    // Phase 2: sequential recurrence (16 independent 8-CTA clusters)
    cudaFuncSetAttribute(rnn_kernel, cudaFuncAttributeMaxDynamicSharedMemorySize,
                         SMEM_B_BYTES);
    rnn_kernel<<<128, 256, SMEM_B_BYTES>>>(rate0, Wh, rate_all);

    // Phase 3: readouts
    readout_kernel<<<32768, 64>>>(rate_all, Wo, bo, Woc, boc, out, outc);
}

// round 3
// speedup vs baseline: 1.8041x; 1.8041x over previous
#include <cuda_runtime.h>
#include <math.h>
#include <stdint.h>

#define T_STEPS 2048
#define BATCH   64
#define IN_DIM  64
#define HID     512
#define O_DIM   32
#define OC_DIM  8

// Scratch: pre[t,b,h] = x@WiT + bi + bh + nscale*noise  (256 MB, static device array)
__device__ float g_pre[(size_t)T_STEPS * BATCH * HID];

// ---------------------------------------------------------------------------
// Kernel A: pre-projection GEMM  [TB=131072, 64] x WiT[64, 512] + biases + noise
// ---------------------------------------------------------------------------
__global__ void pre_kernel(const float* __restrict__ x,
                           const float* __restrict__ Wi,
                           const float* __restrict__ bi,
                           const float* __restrict__ bh,
                           const float* __restrict__ noise) {
    __shared__ float xs[64][64];
    __shared__ float wT[64][68];

    const float NSCALE = sqrtf(45.0f / 512.0f);
    const int m0  = blockIdx.x * 64;
    const int h0  = blockIdx.y * 64;
    const int tid = threadIdx.x;

    const float4* x4 = (const float4*)(x + (size_t)m0 * IN_DIM);
    float4* xs4 = (float4*)xs;
#pragma unroll
    for (int i = 0; i < 4; i++) xs4[tid + 256 * i] = x4[tid + 256 * i];

    for (int i = tid; i < 4096; i += 256) {
        int h = i >> 6, k = i & 63;
        wT[k][h] = Wi[(size_t)(h0 + h) * IN_DIM + k];
    }
    __syncthreads();

    const int hq = tid & 15;
    const int ms = tid >> 4;

    float acc[4][4];
#pragma unroll
    for (int j = 0; j < 4; j++) { acc[j][0] = acc[j][1] = acc[j][2] = acc[j][3] = 0.f; }

#pragma unroll 8
    for (int k = 0; k < 64; k++) {
        float4 w = *(const float4*)&wT[k][hq * 4];
#pragma unroll
        for (int j = 0; j < 4; j++) {
            float xv = xs[ms * 4 + j][k];
            acc[j][0] = fmaf(w.x, xv, acc[j][0]);
            acc[j][1] = fmaf(w.y, xv, acc[j][1]);
            acc[j][2] = fmaf(w.z, xv, acc[j][2]);
            acc[j][3] = fmaf(w.w, xv, acc[j][3]);
        }
    }

    float4 biv = *(const float4*)&bi[h0 + hq * 4];
    float4 bhv = *(const float4*)&bh[h0 + hq * 4];
    float bx = biv.x + bhv.x, by = biv.y + bhv.y, bz = biv.z + bhv.z, bw = biv.w + bhv.w;

#pragma unroll
    for (int j = 0; j < 4; j++) {
        int m = m0 + ms * 4 + j;
        size_t off = (size_t)m * HID + h0 + hq * 4;
        float4 nv = *(const float4*)&noise[off];
        float4 r;
        r.x = acc[j][0] + bx + NSCALE * nv.x;
        r.y = acc[j][1] + by + NSCALE * nv.y;
        r.z = acc[j][2] + bz + NSCALE * nv.z;
        r.w = acc[j][3] + bw + NSCALE * nv.w;
        *(float4*)&g_pre[off] = r;
    }
}

// ---------------------------------------------------------------------------
// Kernel B: recurrence. 16 clusters x 8 CTAs x 256 threads.
// CTA rank r keeps Wh rows [64r,64r+64) in REGISTERS (128 floats/thread as
// 64 f32x2 pairs). Per step: f32x2 GEMM over SMEM rate (broadcast LDS),
// k-partial reduce via SMEM, ex2-tanh update, st.async scalar broadcast of
// rnew to all 8 peers with mbarrier complete_tx, ping-pong mbarriers.
// ---------------------------------------------------------------------------
typedef unsigned long long ull;

#define FMA2(acc, a, b) \
    asm("fma.rn.f32x2 %0, %1, %2, %3;" : "=l"(acc) : "l"(a), "l"(b), "l"(acc))

__device__ __forceinline__ uint32_t smem_u32(const void* p) {
    return (uint32_t)__cvta_generic_to_shared(p);
}

__device__ __forceinline__ void cluster_sync_() {
    asm volatile("barrier.cluster.arrive.aligned;" ::: "memory");
    asm volatile("barrier.cluster.wait.aligned;" ::: "memory");
}

__device__ __forceinline__ float hsum2(ull a) {
    float lo, hi;
    asm("mov.b64 {%0, %1}, %2;" : "=f"(lo), "=f"(hi) : "l"(a));
    return lo + hi;
}

__global__ void __launch_bounds__(256, 1) __cluster_dims__(8, 1, 1)
rnn_kernel(const float* __restrict__ rate0,
           const float* __restrict__ Wh,
           float* __restrict__ rate_all) {
    __shared__ __align__(16) float rate_s[2][4][HID];   // 16 KB double buffer
    __shared__ __align__(16) float part[8][4][64];      // 8 KB k-partials
    __shared__ __align__(8)  ull  mbar[2];

    const int tid    = threadIdx.x;
    const int rank   = blockIdx.x & 7;
    const int cid    = blockIdx.x >> 3;
    const int b0     = cid * 4;
    const int h_base = rank * 64;
    const int kc     = tid >> 5;   // k-chunk 0..7 (64 k each); uniform per warp
    const int hp     = tid & 31;   // h-pair index: rows 2hp, 2hp+1

    if (tid == 0) {
        uint32_t m0 = smem_u32(&mbar[0]), m1 = smem_u32(&mbar[1]);
        asm volatile("mbarrier.init.shared.b64 [%0], 1;" :: "r"(m0) : "memory");
        asm volatile("mbarrier.init.shared.b64 [%0], 1;" :: "r"(m1) : "memory");
        asm volatile("fence.mbarrier_init.release.cluster;" ::: "memory");
        asm volatile("mbarrier.arrive.expect_tx.shared.b64 _, [%0], 8192;" :: "r"(m0) : "memory");
        asm volatile("mbarrier.arrive.expect_tx.shared.b64 _, [%0], 8192;" :: "r"(m1) : "memory");
    }

    // ---- Wh slice into registers: thread owns rows (h_base+2hp, +2hp+1), cols [64kc,64kc+64)
    ull w0[32], w1[32];
    {
        const int r0 = h_base + 2 * hp;
        const ulonglong2* p0 = (const ulonglong2*)(Wh + (size_t)r0 * HID + kc * 64);
        const ulonglong2* p1 = (const ulonglong2*)(Wh + (size_t)(r0 + 1) * HID + kc * 64);
#pragma unroll
        for (int j = 0; j < 16; j++) {
            ulonglong2 a = p0[j]; w0[2 * j] = a.x; w0[2 * j + 1] = a.y;
            ulonglong2 b = p1[j]; w1[2 * j] = b.x; w1[2 * j + 1] = b.y;
        }
    }

    // ---- rate0 into buffer 0 (all 4 batches, full 512)
    for (int i = tid; i < 4 * HID; i += 256)
        rate_s[0][i >> 9][i & 511] = rate0[(size_t)(b0 + (i >> 9)) * HID + (i & 511)];
    __syncthreads();
    cluster_sync_();   // barriers initialized + buffers loaded cluster-wide

    // ---- peer SMEM base addresses (rate_s base mapped into each rank)
    uint32_t rate_u32  = smem_u32(&rate_s[0][0][0]);
    uint32_t bar_delta = smem_u32(&mbar[0]) - rate_u32;
    uint32_t peer[8];
#pragma unroll
    for (int p = 0; p < 8; p++)
        asm volatile("mapa.shared::cluster.u32 %0, %1, %2;"
                     : "=r"(peer[p]) : "r"(rate_u32), "r"(p));

    const int ub = tid >> 6;        // update batch 0..3
    const int uh = tid & 63;        // update h within slice
    const int hg = h_base + uh;

    float pre_next = g_pre[(size_t)(b0 + ub) * HID + hg];

    for (int t = 0; t < T_STEPS; t++) {
        const int cur = t & 1, nxt = cur ^ 1;
        const float pre_cur = pre_next;
        if (t < T_STEPS - 1)
            pre_next = g_pre[((size_t)(t + 1) * BATCH + b0 + ub) * HID + hg];

        // ---- f32x2 GEMM: 8 accumulators (2 h x 4 b), 64-k chunk
        const ulonglong2* rb0 = (const ulonglong2*)&rate_s[cur][0][kc * 64];
        const ulonglong2* rb1 = (const ulonglong2*)&rate_s[cur][1][kc * 64];
        const ulonglong2* rb2 = (const ulonglong2*)&rate_s[cur][2][kc * 64];
        const ulonglong2* rb3 = (const ulonglong2*)&rate_s[cur][3][kc * 64];

        ull a00 = 0, a01 = 0, a02 = 0, a03 = 0;   // row 2hp,   batches 0..3
        ull a10 = 0, a11 = 0, a12 = 0, a13 = 0;   // row 2hp+1, batches 0..3
#pragma unroll
        for (int q = 0; q < 16; q++) {
            ulonglong2 v0 = rb0[q], v1 = rb1[q], v2 = rb2[q], v3 = rb3[q];
            ull wa = w0[2 * q], wb = w0[2 * q + 1];
            ull wc = w1[2 * q], wd = w1[2 * q + 1];
            FMA2(a00, wa, v0.x); FMA2(a01, wa, v1.x); FMA2(a02, wa, v2.x); FMA2(a03, wa, v3.x);
            FMA2(a10, wc, v0.x); FMA2(a11, wc, v1.x); FMA2(a12, wc, v2.x); FMA2(a13, wc, v3.x);
            FMA2(a00, wb, v0.y); FMA2(a01, wb, v1.y); FMA2(a02, wb, v2.y); FMA2(a03, wb, v3.y);
            FMA2(a10, wd, v0.y); FMA2(a11, wd, v1.y); FMA2(a12, wd, v2.y); FMA2(a13, wd, v3.y);
        }
        *(float2*)&part[kc][0][2 * hp] = make_float2(hsum2(a00), hsum2(a10));
        *(float2*)&part[kc][1][2 * hp] = make_float2(hsum2(a01), hsum2(a11));
        *(float2*)&part[kc][2][2 * hp] = make_float2(hsum2(a02), hsum2(a12));
        *(float2*)&part[kc][3][2 * hp] = make_float2(hsum2(a03), hsum2(a13));
        __syncthreads();

        // ---- reduce + leaky tanh update (one (b,h) per thread)
        float s = ((part[0][ub][uh] + part[1][ub][uh])
                 + (part[2][ub][uh] + part[3][ub][uh]))
                + ((part[4][ub][uh] + part[5][ub][uh])
                 + (part[6][ub][uh] + part[7][ub][uh]))
                + pre_cur;
        float e, rc;
        asm("ex2.approx.f32 %0, %1;" : "=f"(e) : "f"(s * 2.8853900817779268f));
        asm("rcp.approx.f32 %0, %1;" : "=f"(rc) : "f"(e + 1.0f));
        float th   = fmaf(-2.0f, rc, 1.0f);   // tanh(s)
        float prev = rate_s[cur][ub][hg];
        float rnew = fmaf(0.9f, prev, 0.1f * th);

        rate_all[((size_t)t * BATCH + b0 + ub) * HID + hg] = rnew;

        // ---- broadcast rnew to all 8 CTAs' buffer[nxt] with tx-completion
        uint32_t doff = (uint32_t)(((nxt * 4 + ub) * HID + hg) * 4);
        uint32_t boff = bar_delta + (uint32_t)(nxt * 8);
        uint32_t rbits = __float_as_uint(rnew);
#pragma unroll
        for (int p = 0; p < 8; p++)
            asm volatile(
                "st.async.weak.shared::cluster.mbarrier::complete_tx::bytes.b32 [%0], %1, [%2];"
                :: "r"(peer[p] + doff), "r"(rbits), "r"(peer[p] + boff) : "memory");

        // ---- wait for next buffer complete (8 KB from 8 CTAs), then re-arm
        {
            uint32_t bw  = smem_u32(&mbar[nxt]);
            uint32_t par = (uint32_t)((t >> 1) & 1);
            uint32_t done;
            asm volatile(
                "{\n\t.reg .pred p;\n\t"
                "mbarrier.try_wait.parity.acquire.cluster.shared::cta.b64 p, [%1], %2;\n\t"
                "selp.b32 %0, 1, 0, p;\n\t}"
                : "=r"(done) : "r"(bw), "r"(par) : "memory");
            if (!done) {
                asm volatile(
                    "{\n\t.reg .pred P1;\n\t"
                    "WL_%=:\n\t"
                    "mbarrier.try_wait.parity.acquire.cluster.shared::cta.b64 P1, [%0], %1, 0x989680;\n\t"
                    "@P1 bra.uni WD_%=;\n\t"
                    "bra.uni WL_%=;\n\t"
                    "WD_%=:\n\t}"
                    :: "r"(bw), "r"(par) : "memory");
            }
            if (tid == 0)
                asm volatile("mbarrier.arrive.expect_tx.shared.b64 _, [%0], 8192;"
                             :: "r"(bw) : "memory");
            // re-arm is ordered before next step's st.async by the __syncthreads
            // between the GEMM partials and the update phase of step t+1.
        }
    }
    cluster_sync_();
}

// ---------------------------------------------------------------------------
// Kernel C: readouts.
// ---------------------------------------------------------------------------
__global__ void readout_kernel(const float* __restrict__ rate_all,
                               const float* __restrict__ Wo,
                               const float* __restrict__ bo,
                               const float* __restrict__ Woc,
                               const float* __restrict__ boc,
                               float* __restrict__ out,
                               float* __restrict__ outc) {
    __shared__ float4 rs[4][128];
    const int row0 = blockIdx.x * 4;
    const int tid  = threadIdx.x;   // 64

    const float4* r4 = (const float4*)(rate_all + (size_t)row0 * HID);
#pragma unroll
    for (int i = 0; i < 8; i++) {
        int idx = tid + 64 * i;
        rs[idx >> 7][idx & 127] = r4[idx];
    }
    __syncthreads();

    if (tid < O_DIM) {
        const float4* w4 = (const float4*)(Wo + (size_t)tid * HID);
        float b = bo[tid];
        float a[4] = {b, b, b, b};
#pragma unroll 4
        for (int k = 0; k < 128; k++) {
            float4 w = w4[k];
#pragma unroll
            for (int r = 0; r < 4; r++) {
                float4 v = rs[r][k];
                a[r] = fmaf(w.x, v.x, a[r]);
                a[r] = fmaf(w.y, v.y, a[r]);
                a[r] = fmaf(w.z, v.z, a[r]);
                a[r] = fmaf(w.w, v.w, a[r]);
            }
        }
#pragma unroll
        for (int r = 0; r < 4; r++)
            out[(size_t)(row0 + r) * O_DIM + tid] = a[r];
    } else if (tid < O_DIM + OC_DIM) {
        const int oc = tid - O_DIM;
        const float4* w4 = (const float4*)(Woc + (size_t)oc * HID);
        float b = boc[oc];
        float a[4] = {b, b, b, b};
#pragma unroll 4
        for (int k = 0; k < 128; k++) {
            float4 w = w4[k];
#pragma unroll
            for (int r = 0; r < 4; r++) {
                float4 v = rs[r][k];
                a[r] = fmaf(w.x, v.x, a[r]);
                a[r] = fmaf(w.y, v.y, a[r]);
                a[r] = fmaf(w.z, v.z, a[r]);
                a[r] = fmaf(w.w, v.w, a[r]);
            }
        }
#pragma unroll
        for (int r = 0; r < 4; r++)
            outc[(size_t)(row0 + r) * OC_DIM + oc] = a[r];
    }
}

// ---------------------------------------------------------------------------
extern "C" void kernel_launch(void* const* d_in, const int* in_sizes, int n_in,
                              void* d_out, int out_size) {
    const float* x     = (const float*)d_in[0];
    const float* rate0 = (const float*)d_in[1];
    const float* noise = (const float*)d_in[2];
    const float* Wi    = (const float*)d_in[3];
    const float* bi    = (const float*)d_in[4];
    const float* Wh    = (const float*)d_in[5];
    const float* bh    = (const float*)d_in[6];
    const float* Wo    = (const float*)d_in[7];
    const float* bo    = (const float*)d_in[8];
    const float* Woc   = (const float*)d_in[9];
    const float* boc   = (const float*)d_in[10];

    float* out      = (float*)d_out;
    float* outc     = out  + (size_t)T_STEPS * BATCH * O_DIM;
    float* rate_all = outc + (size_t)T_STEPS * BATCH * OC_DIM;

    pre_kernel<<<dim3(2048, 8), 256>>>(x, Wi, bi, bh, noise);
    rnn_kernel<<<128, 256>>>(rate0, Wh, rate_all);
    readout_kernel<<<32768, 64>>>(rate_all, Wo, bo, Woc, boc, out, outc);
}